// round 5
// baseline (speedup 1.0000x reference)
#include <cuda_runtime.h>
#include <cuda_fp16.h>
#include <math.h>

#define N_NODES 100000
#define N_EDGES 1600000
#define FULL 0xffffffffu
#define SCAN_BS 1024
#define SCAN_NB ((N_NODES + SCAN_BS - 1) / SCAN_BS)   // 98

// ---------------- scratch (static device globals; no allocations) ----------
__device__ int    g_cnt[N_NODES];
__device__ int    g_cursor[N_NODES];
__device__ int    g_rowstart[N_NODES + 1];
__device__ int    g_bsum[SCAN_NB];
__device__ int    g_bpre[SCAN_NB];
__device__ float  g_deginv[N_NODES];
__device__ int4   g_meta[N_EDGES];               // unsorted {src, dst, wi, 0}
__device__ float4 g_basis[N_EDGES];              // unsorted basis
__device__ int2   g_smeta[N_EDGES];              // dst-sorted {src, wi}
__device__ float4 g_sbasis[N_EDGES];             // dst-sorted basis
__device__ float4 g_h1[N_NODES * 4];             // hidden ping
__device__ float4 g_h2[N_NODES * 4];             // hidden pong
__device__ uint2  g_xwh[N_NODES * 100];          // [N][25][16] fp16 XW (80MB)

// ---------------- prep: basis + CSR build ----------------------------------

__global__ void zero_kernel() {
    int i = blockIdx.x * blockDim.x + threadIdx.x;
    if (i < N_NODES) g_cnt[i] = 0;
}

__global__ void prep_kernel(const float2* __restrict__ attr,
                            const int* __restrict__ src,
                            const int* __restrict__ dst) {
    int e = blockIdx.x * blockDim.x + threadIdx.x;
    if (e >= N_EDGES) return;
    float2 a = attr[e];
    float v0 = a.x * 4.f, v1 = a.y * 4.f;
    float k0f = fminf(fmaxf(floorf(v0), 0.f), 3.f);
    float k1f = fminf(fmaxf(floorf(v1), 0.f), 3.f);
    float f0 = v0 - k0f, f1 = v1 - k1f;
    int k0 = (int)k0f, k1 = (int)k1f;
    float4 b;
    b.x = (1.f - f0) * (1.f - f1);
    b.y = (1.f - f0) * f1;
    b.z = f0 * (1.f - f1);
    b.w = f0 * f1;
    g_basis[e] = b;
    int j = k0 + 5 * k1;
    int d = dst[e];
    g_meta[e] = make_int4(src[e], d, j | ((j + 5) << 8) | ((j + 1) << 16) | ((j + 6) << 24), 0);
    atomicAdd(&g_cnt[d], 1);
}

// per-block exclusive scan (Hillis-Steele inclusive, then subtract self)
__global__ void scan_block_kernel() {
    __shared__ int sh[SCAN_BS];
    int i = blockIdx.x * SCAN_BS + threadIdx.x;
    int v = (i < N_NODES) ? g_cnt[i] : 0;
    sh[threadIdx.x] = v;
    __syncthreads();
#pragma unroll
    for (int off = 1; off < SCAN_BS; off <<= 1) {
        int t = (threadIdx.x >= off) ? sh[threadIdx.x - off] : 0;
        __syncthreads();
        sh[threadIdx.x] += t;
        __syncthreads();
    }
    if (i < N_NODES) g_rowstart[i] = sh[threadIdx.x] - v;
    if (threadIdx.x == SCAN_BS - 1) g_bsum[blockIdx.x] = sh[SCAN_BS - 1];
}

__global__ void scan_top_kernel() {
    if (threadIdx.x == 0) {
        int run = 0;
        for (int b = 0; b < SCAN_NB; b++) { g_bpre[b] = run; run += g_bsum[b]; }
        g_rowstart[N_NODES] = N_EDGES;
    }
}

__global__ void scan_add_kernel() {
    int i = blockIdx.x * blockDim.x + threadIdx.x;
    if (i >= N_NODES) return;
    int rs = g_rowstart[i] + g_bpre[i >> 10];
    g_rowstart[i] = rs;
    g_cursor[i] = rs;
    g_deginv[i] = 1.f / fmaxf((float)g_cnt[i], 1.f);
}

__global__ void scatter_kernel() {
    int e = blockIdx.x * blockDim.x + threadIdx.x;
    if (e >= N_EDGES) return;
    int4 m = g_meta[e];
    int p = atomicAdd(&g_cursor[m.y], 1);
    g_smeta[p] = make_int2(m.x, m.z);
    g_sbasis[p] = g_basis[e];
}

// ---------------- helpers ---------------------------------------------------

__device__ __forceinline__ float2 h2f2(unsigned u) {
    __half2 h = *reinterpret_cast<__half2*>(&u);
    return __half22float2(h);
}

// ---------------- layer 1: pull (in=2), fused node update -------------------
// warp = node; 8 quads process 8 in-edges in parallel; lane l owns ch 4l..4l+3.
__global__ void pull1_kernel(const float2* __restrict__ x,
                             const float* __restrict__ W1,
                             const float* __restrict__ root,
                             const float* __restrict__ bias,
                             float4* __restrict__ hout) {
    __shared__ uint4 Wsh[100];                   // [25][4] fp16 {W[w][0][4l..],W[w][1][4l..]}
    __shared__ float4 rsh[8];                    // [2][4]
    __shared__ float4 bsh[4];
    if (threadIdx.x < 100) {
        int w = threadIdx.x >> 2, l = threadIdx.x & 3;
        const float4* Wv = (const float4*)W1;    // [25][2][4] float4
        float4 a0 = Wv[w * 8 + l];
        float4 a1 = Wv[w * 8 + 4 + l];
        __half2 p0 = __floats2half2_rn(a0.x, a0.y);
        __half2 p1 = __floats2half2_rn(a0.z, a0.w);
        __half2 p2 = __floats2half2_rn(a1.x, a1.y);
        __half2 p3 = __floats2half2_rn(a1.z, a1.w);
        uint4 u;
        u.x = *reinterpret_cast<unsigned*>(&p0);
        u.y = *reinterpret_cast<unsigned*>(&p1);
        u.z = *reinterpret_cast<unsigned*>(&p2);
        u.w = *reinterpret_cast<unsigned*>(&p3);
        Wsh[w * 4 + l] = u;
    }
    if (threadIdx.x < 8) rsh[threadIdx.x] = ((const float4*)root)[threadIdx.x];
    if (threadIdx.x < 4) bsh[threadIdx.x] = ((const float4*)bias)[threadIdx.x];
    __syncthreads();
    int wid = (blockIdx.x * blockDim.x + threadIdx.x) >> 5;
    if (wid >= N_NODES) return;
    int lane = threadIdx.x & 31;
    int q = lane >> 2, l = lane & 3;
    int beg = g_rowstart[wid], end = g_rowstart[wid + 1];
    float4 acc = make_float4(0.f, 0.f, 0.f, 0.f);
    for (int p = beg + q; p < end; p += 8) {
        int2 m = g_smeta[p];                     // quad-broadcast
        float4 b = g_sbasis[p];
        float2 xv = x[m.x];
        float bs[4] = {b.x, b.y, b.z, b.w};
#pragma unroll
        for (int qt = 0; qt < 4; qt++) {
            int w = (m.y >> (8 * qt)) & 0xff;
            uint4 wv = Wsh[w * 4 + l];
            float2 w00 = h2f2(wv.x), w01 = h2f2(wv.y);
            float2 w10 = h2f2(wv.z), w11 = h2f2(wv.w);
            float c0 = bs[qt] * xv.x, c1 = bs[qt] * xv.y;
            acc.x += c0 * w00.x + c1 * w10.x;
            acc.y += c0 * w00.y + c1 * w10.y;
            acc.z += c0 * w01.x + c1 * w11.x;
            acc.w += c0 * w01.y + c1 * w11.y;
        }
    }
#pragma unroll
    for (int s = 16; s >= 4; s >>= 1) {
        acc.x += __shfl_down_sync(FULL, acc.x, s);
        acc.y += __shfl_down_sync(FULL, acc.y, s);
        acc.z += __shfl_down_sync(FULL, acc.z, s);
        acc.w += __shfl_down_sync(FULL, acc.w, s);
    }
    if (lane < 4) {
        float di = g_deginv[wid];
        float2 xv = x[wid];
        float4 r0 = rsh[l], r1 = rsh[4 + l], bb = bsh[l];
        float4 o;
        o.x = fmaxf(bb.x + acc.x * di + xv.x * r0.x + xv.y * r1.x, 0.f);
        o.y = fmaxf(bb.y + acc.y * di + xv.x * r0.y + xv.y * r1.y, 0.f);
        o.z = fmaxf(bb.z + acc.z * di + xv.x * r0.z + xv.y * r1.z, 0.f);
        o.w = fmaxf(bb.w + acc.w * di + xv.x * r0.w + xv.y * r1.w, 0.f);
        hout[(size_t)wid * 4 + l] = o;
    }
}

// ---------------- XW precompute (fp16 out) ----------------------------------
__global__ void xw_kernel(const float4* __restrict__ hin,
                          const float* __restrict__ W) {
    __shared__ float4 hs[400];                   // 100 nodes x 16 floats
    int t = threadIdx.x;
    int n0 = blockIdx.x * 100;
    int k = t >> 2, o4 = t & 3;
    float4 wc[16];
    if (t < 100) {
        const float4* Wv = (const float4*)W;     // [25][16][4]
#pragma unroll
        for (int i = 0; i < 16; i++) wc[i] = Wv[(k * 16 + i) * 4 + o4];
    }
    for (int j = t; j < 400; j += blockDim.x) hs[j] = hin[n0 * 4 + j];
    __syncthreads();
    if (t >= 100) return;
    const float* hsf = (const float*)hs;
    for (int n = 0; n < 100; n++) {
        float4 a = make_float4(0.f, 0.f, 0.f, 0.f);
#pragma unroll
        for (int i = 0; i < 16; i++) {
            float hv = hsf[n * 16 + i];
            a.x += hv * wc[i].x; a.y += hv * wc[i].y;
            a.z += hv * wc[i].z; a.w += hv * wc[i].w;
        }
        __half2 h0 = __floats2half2_rn(a.x, a.y);
        __half2 h1 = __floats2half2_rn(a.z, a.w);
        uint2 u;
        u.x = *reinterpret_cast<unsigned*>(&h0);
        u.y = *reinterpret_cast<unsigned*>(&h1);
        g_xwh[((size_t)(n0 + n) * 25 + k) * 4 + o4] = u;
    }
}

// ---------------- layers 2/3: pull gather, fused node update ----------------
__global__ void pull16_kernel(const float4* __restrict__ hin,
                              const float* __restrict__ root,
                              const float* __restrict__ bias,
                              float4* __restrict__ hout) {
    __shared__ float4 rsh[64];                   // [16][4]
    __shared__ float4 bsh[4];
    for (int j = threadIdx.x; j < 64; j += blockDim.x)
        rsh[j] = ((const float4*)root)[j];
    if (threadIdx.x < 4) bsh[threadIdx.x] = ((const float4*)bias)[threadIdx.x];
    __syncthreads();
    int wid = (blockIdx.x * blockDim.x + threadIdx.x) >> 5;
    if (wid >= N_NODES) return;
    int lane = threadIdx.x & 31;
    int q = lane >> 2, l = lane & 3;
    int beg = g_rowstart[wid], end = g_rowstart[wid + 1];
    float4 acc = make_float4(0.f, 0.f, 0.f, 0.f);
    for (int p = beg + q; p < end; p += 8) {
        int2 m = g_smeta[p];                     // quad-broadcast
        float4 b = g_sbasis[p];
        size_t base = (size_t)m.x * 100;
        float bs[4] = {b.x, b.y, b.z, b.w};
#pragma unroll
        for (int qt = 0; qt < 4; qt++) {
            int w = (m.y >> (8 * qt)) & 0xff;
            uint2 v = g_xwh[base + w * 4 + l];
            float2 f0 = h2f2(v.x), f1 = h2f2(v.y);
            float sq = bs[qt];
            acc.x += sq * f0.x; acc.y += sq * f0.y;
            acc.z += sq * f1.x; acc.w += sq * f1.y;
        }
    }
#pragma unroll
    for (int s = 16; s >= 4; s >>= 1) {
        acc.x += __shfl_down_sync(FULL, acc.x, s);
        acc.y += __shfl_down_sync(FULL, acc.y, s);
        acc.z += __shfl_down_sync(FULL, acc.z, s);
        acc.w += __shfl_down_sync(FULL, acc.w, s);
    }
    if (lane < 4) {
        float di = g_deginv[wid];
        float4 o = bsh[l];
        o.x += acc.x * di; o.y += acc.y * di; o.z += acc.z * di; o.w += acc.w * di;
        const float* h = (const float*)(hin + (size_t)wid * 4);
#pragma unroll
        for (int i = 0; i < 16; i++) {
            float hv = h[i];
            float4 r = rsh[i * 4 + l];
            o.x += hv * r.x; o.y += hv * r.y; o.z += hv * r.z; o.w += hv * r.w;
        }
        o.x = fmaxf(o.x, 0.f); o.y = fmaxf(o.y, 0.f);
        o.z = fmaxf(o.z, 0.f); o.w = fmaxf(o.w, 0.f);
        hout[(size_t)wid * 4 + l] = o;
    }
}

__global__ void final_kernel(const float4* __restrict__ hin,
                             const float* __restrict__ fcw,
                             const float* __restrict__ fcb,
                             float* __restrict__ out) {
    int n = blockIdx.x * blockDim.x + threadIdx.x;
    if (n >= N_NODES) return;
    const float4* h = hin + (size_t)n * 4;
    const float4* w = (const float4*)fcw;
    float z = fcb[0];
#pragma unroll
    for (int j = 0; j < 4; j++) {
        float4 hv = h[j], wv = w[j];
        z += hv.x * wv.x + hv.y * wv.y + hv.z * wv.z + hv.w * wv.w;
    }
    out[n] = 1.f / (1.f + expf(-z));
}

// ---------------- launch ---------------------------------------------------

extern "C" void kernel_launch(void* const* d_in, const int* in_sizes, int n_in,
                              void* d_out, int out_size) {
    const float2* x     = (const float2*)d_in[0];
    const int*    ei    = (const int*)d_in[1];
    const float2* attr  = (const float2*)d_in[2];
    const float*  W1    = (const float*)d_in[3];
    const float*  root1 = (const float*)d_in[4];
    const float*  b1    = (const float*)d_in[5];
    const float*  W2    = (const float*)d_in[6];
    const float*  root2 = (const float*)d_in[7];
    const float*  b2    = (const float*)d_in[8];
    const float*  W3    = (const float*)d_in[9];
    const float*  root3 = (const float*)d_in[10];
    const float*  b3    = (const float*)d_in[11];
    const float*  fcw   = (const float*)d_in[12];
    const float*  fcb   = (const float*)d_in[13];
    const int* src = ei;
    const int* dst = ei + N_EDGES;

    float4 *h1, *h2;
    cudaGetSymbolAddress((void**)&h1, g_h1);
    cudaGetSymbolAddress((void**)&h2, g_h2);

    const int TB = 256;
    int gEdge = (N_EDGES + TB - 1) / TB;
    int gNode = (N_NODES + TB - 1) / TB;
    int gPull = (N_NODES * 32 + TB - 1) / TB;    // warp per node: 12500

    // prep: basis + CSR
    zero_kernel<<<gNode, TB>>>();
    prep_kernel<<<gEdge, TB>>>(attr, src, dst);
    scan_block_kernel<<<SCAN_NB, SCAN_BS>>>();
    scan_top_kernel<<<1, 32>>>();
    scan_add_kernel<<<gNode, TB>>>();
    scatter_kernel<<<gEdge, TB>>>();

    // layer 1 (in=2), fused
    pull1_kernel<<<gPull, TB>>>(x, W1, root1, b1, h1);

    // layer 2
    xw_kernel<<<N_NODES / 100, 128>>>(h1, W2);
    pull16_kernel<<<gPull, TB>>>(h1, root2, b2, h2);

    // layer 3
    xw_kernel<<<N_NODES / 100, 128>>>(h2, W3);
    pull16_kernel<<<gPull, TB>>>(h2, root3, b3, h1);

    final_kernel<<<gNode, TB>>>(h1, fcw, fcb, (float*)d_out);
}

// round 6
// speedup vs baseline: 1.3805x; 1.3805x over previous
#include <cuda_runtime.h>
#include <cuda_fp16.h>
#include <math.h>

#define N_NODES 100000
#define N_EDGES 1600000
#define FULL 0xffffffffu

// ---------------- scratch (static device globals; no allocations) ----------
__device__ float4 g_basis[N_EDGES];              // 4 tensor-product basis vals / edge
__device__ int2   g_meta[N_EDGES];               // {src | j<<20, dst}
__device__ float  g_deg[N_NODES];
__device__ float  g_deginv[N_NODES];
__device__ float4 g_agg[N_NODES * 4];            // [N][16] accumulators
__device__ float4 g_h1[N_NODES * 4];             // hidden ping
__device__ float4 g_h2[N_NODES * 4];             // hidden pong
__device__ uint2  g_xwh[N_NODES * 100];          // [N][25][16] fp16 XW (80MB)

// ---------------- kernels --------------------------------------------------

__global__ void zero_kernel() {
    int i = blockIdx.x * blockDim.x + threadIdx.x;
    if (i < N_NODES * 4) g_agg[i] = make_float4(0.f, 0.f, 0.f, 0.f);
    if (i < N_NODES)     g_deg[i] = 0.f;
}

// basis/knot precompute + degree count (shared across all 3 layers)
__global__ void prep_kernel(const float2* __restrict__ attr,
                            const int* __restrict__ src,
                            const int* __restrict__ dst) {
    int e = blockIdx.x * blockDim.x + threadIdx.x;
    if (e >= N_EDGES) return;
    float2 a = attr[e];
    float v0 = a.x * 4.f, v1 = a.y * 4.f;
    float k0f = fminf(fmaxf(floorf(v0), 0.f), 3.f);
    float k1f = fminf(fmaxf(floorf(v1), 0.f), 3.f);
    float f0 = v0 - k0f, f1 = v1 - k1f;
    int k0 = (int)k0f, k1 = (int)k1f;
    float4 b;
    b.x = (1.f - f0) * (1.f - f1);   // tap j
    b.y = (1.f - f0) * f1;           // tap j+5
    b.z = f0 * (1.f - f1);           // tap j+1
    b.w = f0 * f1;                   // tap j+6
    g_basis[e] = b;
    int j = k0 + 5 * k1;
    int d = dst[e];
    g_meta[e] = make_int2(src[e] | (j << 20), d);
    atomicAdd(&g_deg[d], 1.f);
}

__global__ void recip_kernel() {
    int n = blockIdx.x * blockDim.x + threadIdx.x;
    if (n < N_NODES) g_deginv[n] = 1.f / fmaxf(g_deg[n], 1.f);
}

__device__ __forceinline__ void red_add_v4(float* p, float4 v) {
    asm volatile("red.global.add.v4.f32 [%0], {%1,%2,%3,%4};"
                 :: "l"(p), "f"(v.x), "f"(v.y), "f"(v.z), "f"(v.w) : "memory");
}

__device__ __forceinline__ float2 h2f2(unsigned u) {
    __half2 h = *reinterpret_cast<__half2*>(&u);
    return __half22float2(h);
}

// Layer 1 edge kernel: in=2, 4 threads/edge. W1 in shared as fp16:
// Wsh[w*4+l] = uint4 of 8 halves {W[w][0][4l..4l+3], W[w][1][4l..4l+3]}.
__global__ void edge1_kernel(const float2* __restrict__ x,
                             const float* __restrict__ W1) {
    __shared__ uint4 Wsh[100];                   // [25][4]
    if (threadIdx.x < 100) {
        int w = threadIdx.x >> 2, l = threadIdx.x & 3;
        const float4* Wv = (const float4*)W1;    // [25][2][4] float4
        float4 a0 = Wv[w * 8 + l];
        float4 a1 = Wv[w * 8 + 4 + l];
        __half2 p0 = __floats2half2_rn(a0.x, a0.y);
        __half2 p1 = __floats2half2_rn(a0.z, a0.w);
        __half2 p2 = __floats2half2_rn(a1.x, a1.y);
        __half2 p3 = __floats2half2_rn(a1.z, a1.w);
        uint4 u;
        u.x = *reinterpret_cast<unsigned*>(&p0);
        u.y = *reinterpret_cast<unsigned*>(&p1);
        u.z = *reinterpret_cast<unsigned*>(&p2);
        u.w = *reinterpret_cast<unsigned*>(&p3);
        Wsh[w * 4 + l] = u;
    }
    __syncthreads();
    int t = blockIdx.x * blockDim.x + threadIdx.x;   // E*4 threads exactly
    int e = t >> 2;
    int l = threadIdx.x & 3;
    int2 m = g_meta[e];                          // quad-broadcast, 64B/warp
    float4 b = g_basis[e];
    int s = m.x & 0xFFFFF;
    int j = m.x >> 20;
    float2 xv = x[s];
    const int woff[4] = {0, 5, 1, 6};
    float bs[4] = {b.x, b.y, b.z, b.w};
    float4 acc = make_float4(0.f, 0.f, 0.f, 0.f);
#pragma unroll
    for (int q = 0; q < 4; q++) {
        uint4 wv = Wsh[(j + woff[q]) * 4 + l];
        float2 w00 = h2f2(wv.x), w01 = h2f2(wv.y);
        float2 w10 = h2f2(wv.z), w11 = h2f2(wv.w);
        float c0 = bs[q] * xv.x, c1 = bs[q] * xv.y;
        acc.x += c0 * w00.x + c1 * w10.x;
        acc.y += c0 * w00.y + c1 * w10.y;
        acc.z += c0 * w01.x + c1 * w11.x;
        acc.w += c0 * w01.y + c1 * w11.y;
    }
    red_add_v4((float*)&g_agg[(size_t)m.y * 4 + l], acc);
}

// XW precompute: block = 128 threads, 100 active as (k,o4); W column register-
// resident, h chunk (100 nodes) staged in shared; fp16 output.
__global__ void xw_kernel(const float4* __restrict__ hin,
                          const float* __restrict__ W) {
    __shared__ float4 hs[400];                   // 100 nodes x 16 floats
    int t = threadIdx.x;
    int n0 = blockIdx.x * 100;
    int k = t >> 2, o4 = t & 3;
    float4 wc[16];
    if (t < 100) {
        const float4* Wv = (const float4*)W;     // [25][16][4]
#pragma unroll
        for (int i = 0; i < 16; i++) wc[i] = Wv[(k * 16 + i) * 4 + o4];
    }
    for (int j = t; j < 400; j += blockDim.x) hs[j] = hin[n0 * 4 + j];
    __syncthreads();
    if (t >= 100) return;
    const float* hsf = (const float*)hs;
    for (int n = 0; n < 100; n++) {
        float4 a = make_float4(0.f, 0.f, 0.f, 0.f);
#pragma unroll
        for (int i = 0; i < 16; i++) {
            float hv = hsf[n * 16 + i];          // warp-broadcast LDS
            a.x += hv * wc[i].x; a.y += hv * wc[i].y;
            a.z += hv * wc[i].z; a.w += hv * wc[i].w;
        }
        __half2 h0 = __floats2half2_rn(a.x, a.y);
        __half2 h1 = __floats2half2_rn(a.z, a.w);
        uint2 u;
        u.x = *reinterpret_cast<unsigned*>(&h0);
        u.y = *reinterpret_cast<unsigned*>(&h1);
        g_xwh[((size_t)(n0 + n) * 25 + k) * 4 + o4] = u;
    }
}

// Edge gather for layers 2/3: 4 threads/edge.
// Taps come in adjacent pairs (j,j+1) and (j+5,j+6): each pair is one
// contiguous 64B fp16 block -> quad loads it as 4x uint4 (ONE wavefront,
// 1.25 avg with straddle), halving gather wavefronts vs per-tap loads.
// Lane layout per block: l0 = tapA ch0-7, l1 = tapA ch8-15,
//                        l2 = tapB ch0-7, l3 = tapB ch8-15.
// shfl_xor(2) recombines; lane-permuted red.v4 keeps one 64B atomic quad.
__global__ void edge_gather_kernel() {
    int t = blockIdx.x * blockDim.x + threadIdx.x;
    int e = t >> 2;
    int l = threadIdx.x & 3;
    int2 m = g_meta[e];
    float4 b = g_basis[e];
    int s = m.x & 0xFFFFF;
    int j = m.x >> 20;
    const char* base = (const char*)g_xwh + (size_t)s * 800 + l * 16;
    uint4 v1 = *reinterpret_cast<const uint4*>(base + j * 32);         // taps j, j+1
    uint4 v2 = *reinterpret_cast<const uint4*>(base + (j + 5) * 32);   // taps j+5, j+6
    float cA = (l & 2) ? b.z : b.x;              // tap j / j+1
    float cB = (l & 2) ? b.w : b.y;              // tap j+5 / j+6
    float acc[8];
    const unsigned* u1 = reinterpret_cast<const unsigned*>(&v1);
    const unsigned* u2 = reinterpret_cast<const unsigned*>(&v2);
#pragma unroll
    for (int i = 0; i < 4; i++) {
        float2 f1 = h2f2(u1[i]);
        float2 f2 = h2f2(u2[i]);
        acc[2 * i]     = cA * f1.x + cB * f2.x;
        acc[2 * i + 1] = cA * f1.y + cB * f2.y;
    }
#pragma unroll
    for (int i = 0; i < 8; i++)
        acc[i] += __shfl_xor_sync(FULL, acc[i], 2);
    // lanes 0,1 hold ch0-7 / ch8-15 sums; lanes 2,3 duplicates.
    // l0 -> ch0-3 (+0), l1 -> ch8-11 (+8), l2 -> ch4-7 (+4), l3 -> ch12-15 (+12)
    float* ap = (float*)g_agg + (size_t)m.y * 16 + ((l & 1) << 3) + ((l & 2) << 1);
    float4 out = (l & 2) ? make_float4(acc[4], acc[5], acc[6], acc[7])
                         : make_float4(acc[0], acc[1], acc[2], acc[3]);
    red_add_v4(ap, out);
}

// Node update, layer 1 (root: 2x16): h = relu(agg/deg + x@root + b); zero agg.
__global__ void node1_kernel(const float2* __restrict__ x,
                             const float* __restrict__ root,
                             const float* __restrict__ bias,
                             float4* __restrict__ hout) {
    __shared__ float4 rsh[8];
    __shared__ float4 bsh[4];
    if (threadIdx.x < 8)  rsh[threadIdx.x] = ((const float4*)root)[threadIdx.x];
    if (threadIdx.x < 4)  bsh[threadIdx.x] = ((const float4*)bias)[threadIdx.x];
    __syncthreads();
    int t = blockIdx.x * blockDim.x + threadIdx.x;
    int n = t >> 2;
    if (n >= N_NODES) return;
    int l = t & 3;
    float4 a = g_agg[(size_t)n * 4 + l];
    float di = g_deginv[n];
    float2 xv = x[n];
    float4 r0 = rsh[l], r1 = rsh[4 + l], bb = bsh[l];
    float4 o;
    o.x = fmaxf(bb.x + a.x * di + xv.x * r0.x + xv.y * r1.x, 0.f);
    o.y = fmaxf(bb.y + a.y * di + xv.x * r0.y + xv.y * r1.y, 0.f);
    o.z = fmaxf(bb.z + a.z * di + xv.x * r0.z + xv.y * r1.z, 0.f);
    o.w = fmaxf(bb.w + a.w * di + xv.x * r0.w + xv.y * r1.w, 0.f);
    hout[(size_t)n * 4 + l] = o;
    g_agg[(size_t)n * 4 + l] = make_float4(0.f, 0.f, 0.f, 0.f);
}

// Node update, 16-channel root; 4 threads/node.
__global__ void node16_kernel(const float4* __restrict__ hin,
                              const float* __restrict__ root,
                              const float* __restrict__ bias,
                              float4* __restrict__ hout) {
    __shared__ float4 rsh[64];                   // [16][4]
    __shared__ float4 bsh[4];
    for (int j = threadIdx.x; j < 64; j += blockDim.x)
        rsh[j] = ((const float4*)root)[j];
    if (threadIdx.x < 4) bsh[threadIdx.x] = ((const float4*)bias)[threadIdx.x];
    __syncthreads();
    int t = blockIdx.x * blockDim.x + threadIdx.x;
    int n = t >> 2;
    if (n >= N_NODES) return;
    int l = t & 3;
    float4 a = g_agg[(size_t)n * 4 + l];
    float di = g_deginv[n];
    float4 acc = bsh[l];
    acc.x += a.x * di; acc.y += a.y * di; acc.z += a.z * di; acc.w += a.w * di;
    const float* h = (const float*)(hin + (size_t)n * 4);
#pragma unroll
    for (int i = 0; i < 16; i++) {
        float hv = h[i];
        float4 r = rsh[i * 4 + l];
        acc.x += hv * r.x; acc.y += hv * r.y; acc.z += hv * r.z; acc.w += hv * r.w;
    }
    acc.x = fmaxf(acc.x, 0.f); acc.y = fmaxf(acc.y, 0.f);
    acc.z = fmaxf(acc.z, 0.f); acc.w = fmaxf(acc.w, 0.f);
    hout[(size_t)n * 4 + l] = acc;
    g_agg[(size_t)n * 4 + l] = make_float4(0.f, 0.f, 0.f, 0.f);
}

__global__ void final_kernel(const float4* __restrict__ hin,
                             const float* __restrict__ fcw,
                             const float* __restrict__ fcb,
                             float* __restrict__ out) {
    int n = blockIdx.x * blockDim.x + threadIdx.x;
    if (n >= N_NODES) return;
    const float4* h = hin + (size_t)n * 4;
    const float4* w = (const float4*)fcw;
    float z = fcb[0];
#pragma unroll
    for (int j = 0; j < 4; j++) {
        float4 hv = h[j], wv = w[j];
        z += hv.x * wv.x + hv.y * wv.y + hv.z * wv.z + hv.w * wv.w;
    }
    out[n] = 1.f / (1.f + expf(-z));
}

// ---------------- launch ---------------------------------------------------

extern "C" void kernel_launch(void* const* d_in, const int* in_sizes, int n_in,
                              void* d_out, int out_size) {
    const float2* x     = (const float2*)d_in[0];
    const int*    ei    = (const int*)d_in[1];
    const float2* attr  = (const float2*)d_in[2];
    const float*  W1    = (const float*)d_in[3];
    const float*  root1 = (const float*)d_in[4];
    const float*  b1    = (const float*)d_in[5];
    const float*  W2    = (const float*)d_in[6];
    const float*  root2 = (const float*)d_in[7];
    const float*  b2    = (const float*)d_in[8];
    const float*  W3    = (const float*)d_in[9];
    const float*  root3 = (const float*)d_in[10];
    const float*  b3    = (const float*)d_in[11];
    const float*  fcw   = (const float*)d_in[12];
    const float*  fcb   = (const float*)d_in[13];
    const int* src = ei;
    const int* dst = ei + N_EDGES;

    float4 *h1, *h2;
    cudaGetSymbolAddress((void**)&h1, g_h1);
    cudaGetSymbolAddress((void**)&h2, g_h2);

    const int TB = 256;
    int gZero  = (N_NODES * 4 + TB - 1) / TB;
    int gEdge  = (N_EDGES + TB - 1) / TB;
    int gEdge4 = (N_EDGES * 4) / TB;             // exact: 25000
    int gNode4 = (N_NODES * 4 + TB - 1) / TB;
    int gNode  = (N_NODES + TB - 1) / TB;

    zero_kernel<<<gZero, TB>>>();
    prep_kernel<<<gEdge, TB>>>(attr, src, dst);
    recip_kernel<<<gNode, TB>>>();

    // layer 1 (in=2)
    edge1_kernel<<<gEdge4, TB>>>(x, W1);
    node1_kernel<<<gNode4, TB>>>(x, root1, b1, h1);

    // layer 2
    xw_kernel<<<N_NODES / 100, 128>>>(h1, W2);
    edge_gather_kernel<<<gEdge4, TB>>>();
    node16_kernel<<<gNode4, TB>>>(h1, root2, b2, h2);

    // layer 3
    xw_kernel<<<N_NODES / 100, 128>>>(h2, W3);
    edge_gather_kernel<<<gEdge4, TB>>>();
    node16_kernel<<<gNode4, TB>>>(h2, root3, b3, h1);

    final_kernel<<<gNode, TB>>>(h1, fcw, fcb, (float*)d_out);
}

// round 7
// speedup vs baseline: 1.4247x; 1.0320x over previous
#include <cuda_runtime.h>
#include <cuda_fp16.h>
#include <math.h>

#define N_NODES 100000
#define N_EDGES 1600000
#define FULL 0xffffffffu

// ---------------- scratch (static device globals; no allocations) ----------
// Edge record: {src | j<<20, dst, half2(bA0,bB0), half2(bA1,bB1)}
//   bA0 = basis tap j,   bB0 = tap j+5   (pair base)
//   bA1 = basis tap j+1, bB1 = tap j+6   (pair upper)
__device__ int4   g_edge[N_EDGES];
__device__ float  g_deg[N_NODES];
__device__ float4 g_agg[N_NODES * 4];            // [N][16]; invariant: zero at call entry/exit
__device__ float4 g_h1[N_NODES * 4];             // hidden ping
__device__ float4 g_h2[N_NODES * 4];             // hidden pong
__device__ uint2  g_xwh[N_NODES * 100];          // [N][25][16] fp16 XW (80MB)

// ---------------- kernels --------------------------------------------------

__global__ void zero_deg_kernel() {
    int i = blockIdx.x * blockDim.x + threadIdx.x;
    if (i < N_NODES) g_deg[i] = 0.f;
}

// basis/knot precompute + degree count (shared across all 3 layers)
__global__ void prep_kernel(const float2* __restrict__ attr,
                            const int* __restrict__ src,
                            const int* __restrict__ dst) {
    int e = blockIdx.x * blockDim.x + threadIdx.x;
    if (e >= N_EDGES) return;
    float2 a = attr[e];
    float v0 = a.x * 4.f, v1 = a.y * 4.f;
    float k0f = fminf(fmaxf(floorf(v0), 0.f), 3.f);
    float k1f = fminf(fmaxf(floorf(v1), 0.f), 3.f);
    float f0 = v0 - k0f, f1 = v1 - k1f;
    int k0 = (int)k0f, k1 = (int)k1f;
    float bj  = (1.f - f0) * (1.f - f1);   // tap j
    float bj5 = (1.f - f0) * f1;           // tap j+5
    float bj1 = f0 * (1.f - f1);           // tap j+1
    float bj6 = f0 * f1;                   // tap j+6
    int j = k0 + 5 * k1;
    int d = dst[e];
    __half2 p0 = __floats2half2_rn(bj,  bj5);
    __half2 p1 = __floats2half2_rn(bj1, bj6);
    int4 rec;
    rec.x = src[e] | (j << 20);
    rec.y = d;
    rec.z = *reinterpret_cast<int*>(&p0);
    rec.w = *reinterpret_cast<int*>(&p1);
    g_edge[e] = rec;
    atomicAdd(&g_deg[d], 1.f);
}

__device__ __forceinline__ void red_add_v4(float* p, float4 v) {
    asm volatile("red.global.add.v4.f32 [%0], {%1,%2,%3,%4};"
                 :: "l"(p), "f"(v.x), "f"(v.y), "f"(v.z), "f"(v.w) : "memory");
}

__device__ __forceinline__ float2 h2f2(unsigned u) {
    __half2 h = *reinterpret_cast<__half2*>(&u);
    return __half22float2(h);
}

// Layer 1 edge kernel: in=2, 4 threads/edge. W1 in shared as fp16:
// Wsh[w*4+l] = uint4 of 8 halves {W[w][0][4l..4l+3], W[w][1][4l..4l+3]}.
__global__ void edge1_kernel(const float2* __restrict__ x,
                             const float* __restrict__ W1) {
    __shared__ uint4 Wsh[100];                   // [25][4]
    if (threadIdx.x < 100) {
        int w = threadIdx.x >> 2, l = threadIdx.x & 3;
        const float4* Wv = (const float4*)W1;    // [25][2][4] float4
        float4 a0 = Wv[w * 8 + l];
        float4 a1 = Wv[w * 8 + 4 + l];
        __half2 p0 = __floats2half2_rn(a0.x, a0.y);
        __half2 p1 = __floats2half2_rn(a0.z, a0.w);
        __half2 p2 = __floats2half2_rn(a1.x, a1.y);
        __half2 p3 = __floats2half2_rn(a1.z, a1.w);
        uint4 u;
        u.x = *reinterpret_cast<unsigned*>(&p0);
        u.y = *reinterpret_cast<unsigned*>(&p1);
        u.z = *reinterpret_cast<unsigned*>(&p2);
        u.w = *reinterpret_cast<unsigned*>(&p3);
        Wsh[w * 4 + l] = u;
    }
    __syncthreads();
    int t = blockIdx.x * blockDim.x + threadIdx.x;   // E*4 threads exactly
    int e = t >> 2;
    int l = threadIdx.x & 3;
    int4 rec = g_edge[e];                        // quad-broadcast, 128B/warp
    int s = rec.x & 0xFFFFF;
    int j = rec.x >> 20;
    float2 b0 = h2f2(rec.z);                     // {b_j, b_j+5}
    float2 b1 = h2f2(rec.w);                     // {b_j+1, b_j+6}
    float2 xv = x[s];
    const int woff[4] = {0, 5, 1, 6};
    float bs[4] = {b0.x, b0.y, b1.x, b1.y};
    float4 acc = make_float4(0.f, 0.f, 0.f, 0.f);
#pragma unroll
    for (int q = 0; q < 4; q++) {
        uint4 wv = Wsh[(j + woff[q]) * 4 + l];
        float2 w00 = h2f2(wv.x), w01 = h2f2(wv.y);
        float2 w10 = h2f2(wv.z), w11 = h2f2(wv.w);
        float c0 = bs[q] * xv.x, c1 = bs[q] * xv.y;
        acc.x += c0 * w00.x + c1 * w10.x;
        acc.y += c0 * w00.y + c1 * w10.y;
        acc.z += c0 * w01.x + c1 * w11.x;
        acc.w += c0 * w01.y + c1 * w11.y;
    }
    red_add_v4((float*)&g_agg[(size_t)rec.y * 4 + l], acc);
}

// XW precompute: block = 128 threads, 100 active as (k,o4); W column register-
// resident, h chunk (100 nodes) staged in shared; fp16 output.
__global__ void xw_kernel(const float4* __restrict__ hin,
                          const float* __restrict__ W) {
    __shared__ float4 hs[400];                   // 100 nodes x 16 floats
    int t = threadIdx.x;
    int n0 = blockIdx.x * 100;
    int k = t >> 2, o4 = t & 3;
    float4 wc[16];
    if (t < 100) {
        const float4* Wv = (const float4*)W;     // [25][16][4]
#pragma unroll
        for (int i = 0; i < 16; i++) wc[i] = Wv[(k * 16 + i) * 4 + o4];
    }
    for (int j = t; j < 400; j += blockDim.x) hs[j] = hin[n0 * 4 + j];
    __syncthreads();
    if (t >= 100) return;
    const float* hsf = (const float*)hs;
    for (int n = 0; n < 100; n++) {
        float4 a = make_float4(0.f, 0.f, 0.f, 0.f);
#pragma unroll
        for (int i = 0; i < 16; i++) {
            float hv = hsf[n * 16 + i];          // warp-broadcast LDS
            a.x += hv * wc[i].x; a.y += hv * wc[i].y;
            a.z += hv * wc[i].z; a.w += hv * wc[i].w;
        }
        __half2 h0 = __floats2half2_rn(a.x, a.y);
        __half2 h1 = __floats2half2_rn(a.z, a.w);
        uint2 u;
        u.x = *reinterpret_cast<unsigned*>(&h0);
        u.y = *reinterpret_cast<unsigned*>(&h1);
        g_xwh[((size_t)(n0 + n) * 25 + k) * 4 + o4] = u;
    }
}

// Edge gather for layers 2/3: 4 threads/edge.
// Adjacent tap pairs (j,j+1) and (j+5,j+6) are contiguous 64B fp16 blocks:
// each quad loads one block per pair (lanes 0,1 = tapA ch0-7/ch8-15,
// lanes 2,3 = tapB same), shfl_xor(2) recombines, lane-permuted red.v4
// keeps the single contiguous 64B atomic per edge.
__global__ void edge_gather_kernel() {
    int t = blockIdx.x * blockDim.x + threadIdx.x;
    int e = t >> 2;
    int l = threadIdx.x & 3;
    int4 rec = g_edge[e];
    int s = rec.x & 0xFFFFF;
    int j = rec.x >> 20;
    float2 b0 = h2f2(rec.z);                     // {b_j, b_j+5}
    float2 b1 = h2f2(rec.w);                     // {b_j+1, b_j+6}
    const char* base = (const char*)g_xwh + (size_t)s * 800 + l * 16;
    uint4 v1 = *reinterpret_cast<const uint4*>(base + j * 32);         // taps j, j+1
    uint4 v2 = *reinterpret_cast<const uint4*>(base + (j + 5) * 32);   // taps j+5, j+6
    float cA = (l & 2) ? b1.x : b0.x;            // tap j / j+1
    float cB = (l & 2) ? b1.y : b0.y;            // tap j+5 / j+6
    float acc[8];
    const unsigned* u1 = reinterpret_cast<const unsigned*>(&v1);
    const unsigned* u2 = reinterpret_cast<const unsigned*>(&v2);
#pragma unroll
    for (int i = 0; i < 4; i++) {
        float2 f1 = h2f2(u1[i]);
        float2 f2 = h2f2(u2[i]);
        acc[2 * i]     = cA * f1.x + cB * f2.x;
        acc[2 * i + 1] = cA * f1.y + cB * f2.y;
    }
#pragma unroll
    for (int i = 0; i < 8; i++)
        acc[i] += __shfl_xor_sync(FULL, acc[i], 2);
    float* ap = (float*)g_agg + (size_t)rec.y * 16 + ((l & 1) << 3) + ((l & 2) << 1);
    float4 out = (l & 2) ? make_float4(acc[4], acc[5], acc[6], acc[7])
                         : make_float4(acc[0], acc[1], acc[2], acc[3]);
    red_add_v4(ap, out);
}

// Node update, layer 1 (root: 2x16): h = relu(agg/deg + x@root + b); zero agg.
__global__ void node1_kernel(const float2* __restrict__ x,
                             const float* __restrict__ root,
                             const float* __restrict__ bias,
                             float4* __restrict__ hout) {
    __shared__ float4 rsh[8];
    __shared__ float4 bsh[4];
    if (threadIdx.x < 8)  rsh[threadIdx.x] = ((const float4*)root)[threadIdx.x];
    if (threadIdx.x < 4)  bsh[threadIdx.x] = ((const float4*)bias)[threadIdx.x];
    __syncthreads();
    int t = blockIdx.x * blockDim.x + threadIdx.x;
    int n = t >> 2;
    if (n >= N_NODES) return;
    int l = t & 3;
    float4 a = g_agg[(size_t)n * 4 + l];
    float di = 1.f / fmaxf(g_deg[n], 1.f);
    float2 xv = x[n];
    float4 r0 = rsh[l], r1 = rsh[4 + l], bb = bsh[l];
    float4 o;
    o.x = fmaxf(bb.x + a.x * di + xv.x * r0.x + xv.y * r1.x, 0.f);
    o.y = fmaxf(bb.y + a.y * di + xv.x * r0.y + xv.y * r1.y, 0.f);
    o.z = fmaxf(bb.z + a.z * di + xv.x * r0.z + xv.y * r1.z, 0.f);
    o.w = fmaxf(bb.w + a.w * di + xv.x * r0.w + xv.y * r1.w, 0.f);
    hout[(size_t)n * 4 + l] = o;
    g_agg[(size_t)n * 4 + l] = make_float4(0.f, 0.f, 0.f, 0.f);
}

// Node update, 16-channel root; 4 threads/node.
__global__ void node16_kernel(const float4* __restrict__ hin,
                              const float* __restrict__ root,
                              const float* __restrict__ bias,
                              float4* __restrict__ hout) {
    __shared__ float4 rsh[64];                   // [16][4]
    __shared__ float4 bsh[4];
    for (int j = threadIdx.x; j < 64; j += blockDim.x)
        rsh[j] = ((const float4*)root)[j];
    if (threadIdx.x < 4) bsh[threadIdx.x] = ((const float4*)bias)[threadIdx.x];
    __syncthreads();
    int t = blockIdx.x * blockDim.x + threadIdx.x;
    int n = t >> 2;
    if (n >= N_NODES) return;
    int l = t & 3;
    float4 a = g_agg[(size_t)n * 4 + l];
    float di = 1.f / fmaxf(g_deg[n], 1.f);
    float4 acc = bsh[l];
    acc.x += a.x * di; acc.y += a.y * di; acc.z += a.z * di; acc.w += a.w * di;
    const float* h = (const float*)(hin + (size_t)n * 4);
#pragma unroll
    for (int i = 0; i < 16; i++) {
        float hv = h[i];
        float4 r = rsh[i * 4 + l];
        acc.x += hv * r.x; acc.y += hv * r.y; acc.z += hv * r.z; acc.w += hv * r.w;
    }
    acc.x = fmaxf(acc.x, 0.f); acc.y = fmaxf(acc.y, 0.f);
    acc.z = fmaxf(acc.z, 0.f); acc.w = fmaxf(acc.w, 0.f);
    hout[(size_t)n * 4 + l] = acc;
    g_agg[(size_t)n * 4 + l] = make_float4(0.f, 0.f, 0.f, 0.f);
}

// Layer-3 node update fused with fc head: relu(...) -> dot fc_w -> sigmoid.
__global__ void node16_final_kernel(const float4* __restrict__ hin,
                                    const float* __restrict__ root,
                                    const float* __restrict__ bias,
                                    const float* __restrict__ fcw,
                                    const float* __restrict__ fcb,
                                    float* __restrict__ out) {
    __shared__ float4 rsh[64];                   // [16][4]
    __shared__ float4 bsh[4];
    __shared__ float4 wsh[4];
    for (int j = threadIdx.x; j < 64; j += blockDim.x)
        rsh[j] = ((const float4*)root)[j];
    if (threadIdx.x < 4) {
        bsh[threadIdx.x] = ((const float4*)bias)[threadIdx.x];
        wsh[threadIdx.x] = ((const float4*)fcw)[threadIdx.x];
    }
    __syncthreads();
    int t = blockIdx.x * blockDim.x + threadIdx.x;
    int n = t >> 2;
    if (n >= N_NODES) return;
    int l = t & 3;
    float4 a = g_agg[(size_t)n * 4 + l];
    float di = 1.f / fmaxf(g_deg[n], 1.f);
    float4 acc = bsh[l];
    acc.x += a.x * di; acc.y += a.y * di; acc.z += a.z * di; acc.w += a.w * di;
    const float* h = (const float*)(hin + (size_t)n * 4);
#pragma unroll
    for (int i = 0; i < 16; i++) {
        float hv = h[i];
        float4 r = rsh[i * 4 + l];
        acc.x += hv * r.x; acc.y += hv * r.y; acc.z += hv * r.z; acc.w += hv * r.w;
    }
    acc.x = fmaxf(acc.x, 0.f); acc.y = fmaxf(acc.y, 0.f);
    acc.z = fmaxf(acc.z, 0.f); acc.w = fmaxf(acc.w, 0.f);
    g_agg[(size_t)n * 4 + l] = make_float4(0.f, 0.f, 0.f, 0.f);
    float4 wv = wsh[l];
    float z = acc.x * wv.x + acc.y * wv.y + acc.z * wv.z + acc.w * wv.w;
    z += __shfl_xor_sync(FULL, z, 1);
    z += __shfl_xor_sync(FULL, z, 2);
    if (l == 0) out[n] = 1.f / (1.f + expf(-(z + fcb[0])));
}

// ---------------- launch ---------------------------------------------------

extern "C" void kernel_launch(void* const* d_in, const int* in_sizes, int n_in,
                              void* d_out, int out_size) {
    const float2* x     = (const float2*)d_in[0];
    const int*    ei    = (const int*)d_in[1];
    const float2* attr  = (const float2*)d_in[2];
    const float*  W1    = (const float*)d_in[3];
    const float*  root1 = (const float*)d_in[4];
    const float*  b1    = (const float*)d_in[5];
    const float*  W2    = (const float*)d_in[6];
    const float*  root2 = (const float*)d_in[7];
    const float*  b2    = (const float*)d_in[8];
    const float*  W3    = (const float*)d_in[9];
    const float*  root3 = (const float*)d_in[10];
    const float*  b3    = (const float*)d_in[11];
    const float*  fcw   = (const float*)d_in[12];
    const float*  fcb   = (const float*)d_in[13];
    const int* src = ei;
    const int* dst = ei + N_EDGES;

    float4 *h1, *h2;
    cudaGetSymbolAddress((void**)&h1, g_h1);
    cudaGetSymbolAddress((void**)&h2, g_h2);

    const int TB = 256;
    int gEdge  = (N_EDGES + TB - 1) / TB;
    int gEdge4 = (N_EDGES * 4) / TB;             // exact: 25000
    int gNode4 = (N_NODES * 4 + TB - 1) / TB;
    int gNode  = (N_NODES + TB - 1) / TB;

    zero_deg_kernel<<<gNode, TB>>>();
    prep_kernel<<<gEdge, TB>>>(attr, src, dst);

    // layer 1 (in=2)
    edge1_kernel<<<gEdge4, TB>>>(x, W1);
    node1_kernel<<<gNode4, TB>>>(x, root1, b1, h1);

    // layer 2
    xw_kernel<<<N_NODES / 100, 128>>>(h1, W2);
    edge_gather_kernel<<<gEdge4, TB>>>();
    node16_kernel<<<gNode4, TB>>>(h1, root2, b2, h2);

    // layer 3 (node update fused with fc head)
    xw_kernel<<<N_NODES / 100, 128>>>(h2, W3);
    edge_gather_kernel<<<gEdge4, TB>>>();
    node16_final_kernel<<<gNode4, TB>>>(h2, root3, b3, fcw, fcb, (float*)d_out);
}